// round 1
// baseline (speedup 1.0000x reference)
#include <cuda_runtime.h>

// BQNN_hardware: per-row 14 Givens rotations on columns 0 and 3 of a 6x6
// complex unitary, then 15 pair amplitudes, L2-normalized, abs output.
//
// Key algebraic reduction: rotations act on rows of U, so the two needed
// columns (0 and 3) evolve independently as complex 6-vectors starting from
// e0 and e3. We never materialize U.

#define NROT 14
#define NPAIR 15

__global__ __launch_bounds__(256)
void bqnn_kernel(const float* __restrict__ x,
                 const float* __restrict__ pphi,
                 const float* __restrict__ pth,
                 const float* __restrict__ kin,
                 const float* __restrict__ bin,
                 float* __restrict__ out,
                 int B)
{
    int row = blockIdx.x * blockDim.x + threadIdx.x;
    if (row >= B) return;

    // ---- load and scale the 12 inputs (3x float4, fully coalesced lines) ----
    const float4* xp = reinterpret_cast<const float4*>(x + (size_t)row * 12);
    float4 q0 = xp[0], q1 = xp[1], q2 = xp[2];
    float xs[12];
    xs[0]=q0.x; xs[1]=q0.y; xs[2]=q0.z; xs[3]=q0.w;
    xs[4]=q1.x; xs[5]=q1.y; xs[6]=q1.z; xs[7]=q1.w;
    xs[8]=q2.x; xs[9]=q2.y; xs[10]=q2.z; xs[11]=q2.w;
    #pragma unroll
    for (int i = 0; i < 12; i++)
        xs[i] = fmaf(xs[i], __ldg(kin + i), __ldg(bin + i));

    // ---- angle schedules ----
    // theta = [pth[0:4], xs[3:6], pth[4:6], xs[9:12], pth[6:8]]
    // phi   = [0,0,0,0,  xs[0:3], pphi[0:2], xs[6:9], pphi[2:4]]
    float th[NROT], ph[NROT];
    th[0]=__ldg(pth+0); th[1]=__ldg(pth+1); th[2]=__ldg(pth+2); th[3]=__ldg(pth+3);
    th[4]=xs[3]; th[5]=xs[4]; th[6]=xs[5];
    th[7]=__ldg(pth+4); th[8]=__ldg(pth+5);
    th[9]=xs[9]; th[10]=xs[10]; th[11]=xs[11];
    th[12]=__ldg(pth+6); th[13]=__ldg(pth+7);

    ph[0]=0.f; ph[1]=0.f; ph[2]=0.f; ph[3]=0.f;
    ph[4]=xs[0]; ph[5]=xs[1]; ph[6]=xs[2];
    ph[7]=__ldg(pphi+0); ph[8]=__ldg(pphi+1);
    ph[9]=xs[6]; ph[10]=xs[7]; ph[11]=xs[8];
    ph[12]=__ldg(pphi+2); ph[13]=__ldg(pphi+3);

    // ---- two tracked columns of U: va = U e0, vb = U e3 ----
    float2 va[6], vb[6];
    #pragma unroll
    for (int i = 0; i < 6; i++) { va[i] = make_float2(0.f, 0.f); vb[i] = make_float2(0.f, 0.f); }
    va[0].x = 1.f;
    vb[3].x = 1.f;

    const int MI[NROT] = {0,4,1,3, 0,2,4,1,3, 0,2,4,1,3};
    const int MJ[NROT] = {1,5,2,4, 1,3,5,2,4, 1,3,5,2,4};

    #pragma unroll
    for (int k = 0; k < NROT; k++) {
        float st, ct, sp, cp;
        __sincosf(th[k], &st, &ct);
        if (k < 4) { sp = 0.f; cp = 1.f; }       // phi == 0 exactly -> ep = 1
        else       { __sincosf(ph[k], &sp, &cp); }
        const int i = MI[k], j = MJ[k];

        // new_i = ep*ct*vi - st*vj ;  new_j = ep*st*vi + ct*vj
        // factor: w = ep*vi, then real scales by ct/st.
        {
            float2 vi = va[i], vj = va[j];
            float2 w;
            w.x = cp * vi.x - sp * vi.y;
            w.y = cp * vi.y + sp * vi.x;
            va[i].x = fmaf(ct, w.x, -st * vj.x);
            va[i].y = fmaf(ct, w.y, -st * vj.y);
            va[j].x = fmaf(st, w.x,  ct * vj.x);
            va[j].y = fmaf(st, w.y,  ct * vj.y);
        }
        {
            float2 vi = vb[i], vj = vb[j];
            float2 w;
            w.x = cp * vi.x - sp * vi.y;
            w.y = cp * vi.y + sp * vi.x;
            vb[i].x = fmaf(ct, w.x, -st * vj.x);
            vb[i].y = fmaf(ct, w.y, -st * vj.y);
            vb[j].x = fmaf(st, w.x,  ct * vj.x);
            vb[j].y = fmaf(st, w.y,  ct * vj.y);
        }
    }

    // ---- 15 pair amplitudes: amp = va[i]*vb[j] + va[j]*vb[i] (complex) ----
    const int OA[NPAIR] = {0,0,0,0,0,1,1,1,1,2,2,2,3,3,4};
    const int OB[NPAIR] = {1,2,3,4,5,2,3,4,5,3,4,5,4,5,5};

    float m2[NPAIR];
    float s = 0.f;
    #pragma unroll
    for (int p = 0; p < NPAIR; p++) {
        const int i = OA[p], j = OB[p];
        float ax = va[i].x * vb[j].x - va[i].y * vb[j].y
                 + va[j].x * vb[i].x - va[j].y * vb[i].y;
        float ay = va[i].x * vb[j].y + va[i].y * vb[j].x
                 + va[j].x * vb[i].y + va[j].y * vb[i].x;
        m2[p] = fmaf(ax, ax, ay * ay);
        s += m2[p];
    }

    float norm = sqrtf(s);
    float inv = 1.f / fmaxf(norm, 1e-12f);

    float* o = out + (size_t)row * NPAIR;
    #pragma unroll
    for (int p = 0; p < NPAIR; p++)
        o[p] = sqrtf(m2[p]) * inv;
}

extern "C" void kernel_launch(void* const* d_in, const int* in_sizes, int n_in,
                              void* d_out, int out_size)
{
    const float* x    = (const float*)d_in[0];
    const float* pphi = (const float*)d_in[1];
    const float* pth  = (const float*)d_in[2];
    const float* kin  = (const float*)d_in[3];
    const float* bin  = (const float*)d_in[4];
    float* out = (float*)d_out;

    int B = in_sizes[0] / 12;
    int threads = 256;
    int blocks = (B + threads - 1) / threads;
    bqnn_kernel<<<blocks, threads>>>(x, pphi, pth, kin, bin, out, B);
}

// round 4
// speedup vs baseline: 1.9071x; 1.9071x over previous
#include <cuda_runtime.h>

// BQNN_hardware: per-row Givens-rotation chain on columns 0 and 3 of a 6x6
// complex unitary, then 15 pair amplitudes, L2-normalized, abs output.
//
// Optimizations vs R1:
//  - first 4 rotations (phi==0, basis-vector state) folded into closed-form
//    real initial state; pth[1] provably drops out.
//  - 12 uniform param sincos + k/b scale params computed once per block into
//    smem (kills 24 redundant MUFU + 28 uniform LDG wavefronts per warp).
//  - outputs staged in smem, written as coalesced float4 (kills the stride-60B
//    scattered-STG L1 wavefront storm: ~225 -> ~15 wavefronts/warp).
//  - sqrt(m2)/norm -> sqrt(m2 * rcp(max(s,eps^2))) via MUFU.RSQ trick.

#define NPAIR 15
#define TPB 256

__global__ __launch_bounds__(TPB)
void bqnn_kernel(const float* __restrict__ x,
                 const float* __restrict__ pphi,
                 const float* __restrict__ pth,
                 const float* __restrict__ kin,
                 const float* __restrict__ bin,
                 float* __restrict__ out,
                 int B)
{
    __shared__ float s_sin[12], s_cos[12];   // sincos of pth[0..7], pphi[0..3]
    __shared__ float s_k[12], s_b[12];
    __shared__ float s_out[TPB * NPAIR];     // 15360 B staging

    const int tid = threadIdx.x;
    const int row = blockIdx.x * TPB + tid;

    // ---- per-block uniform precompute ----
    if (tid < 12) {
        float a = (tid < 8) ? pth[tid] : pphi[tid - 8];
        float s, c;
        __sincosf(a, &s, &c);
        s_sin[tid] = s; s_cos[tid] = c;
        s_k[tid] = kin[tid];
        s_b[tid] = bin[tid];
    }
    __syncthreads();

    if (row < B) {
        // ---- load + scale the 12 inputs ----
        const float4* xp = reinterpret_cast<const float4*>(x + (size_t)row * 12);
        float4 q0 = xp[0], q1 = xp[1], q2 = xp[2];
        float xs[12];
        xs[0]=q0.x; xs[1]=q0.y; xs[2]=q0.z; xs[3]=q0.w;
        xs[4]=q1.x; xs[5]=q1.y; xs[6]=q1.z; xs[7]=q1.w;
        xs[8]=q2.x; xs[9]=q2.y; xs[10]=q2.z; xs[11]=q2.w;
        #pragma unroll
        for (int i = 0; i < 12; i++)
            xs[i] = fmaf(xs[i], s_k[i], s_b[i]);

        // ---- per-thread sincos of the 12 data angles ----
        float ds[12], dc[12];
        #pragma unroll
        for (int i = 0; i < 12; i++)
            __sincosf(xs[i], &ds[i], &dc[i]);

        // ---- folded initial state (rotations k=0..3, phi=0, basis vectors) ----
        // va = (c0, c2*s0, s2*s0, 0,0,0) real ; vb = (0,0,0, c3, s3, 0) real
        float2 va[6], vb[6];
        #pragma unroll
        for (int i = 0; i < 6; i++) {
            va[i] = make_float2(0.f, 0.f);
            vb[i] = make_float2(0.f, 0.f);
        }
        va[0].x = s_cos[0];
        va[1].x = s_cos[2] * s_sin[0];
        va[2].x = s_sin[2] * s_sin[0];
        vb[3].x = s_cos[3];
        vb[4].x = s_sin[3];

        // complex Givens rotation on rows (i,j) of both tracked columns:
        // vi' = e^{i phi} ct vi - st vj ; vj' = e^{i phi} st vi + ct vj
        #define ROT(I, J, ST, CT, SP, CP)                                   \
        do {                                                                \
            {                                                               \
                float2 vi = va[I], vj = va[J];                              \
                float wx = (CP) * vi.x - (SP) * vi.y;                       \
                float wy = fmaf((CP), vi.y, (SP) * vi.x);                   \
                va[I].x = fmaf((CT), wx, -(ST) * vj.x);                     \
                va[I].y = fmaf((CT), wy, -(ST) * vj.y);                     \
                va[J].x = fmaf((ST), wx,  (CT) * vj.x);                     \
                va[J].y = fmaf((ST), wy,  (CT) * vj.y);                     \
            }                                                               \
            {                                                               \
                float2 vi = vb[I], vj = vb[J];                              \
                float wx = (CP) * vi.x - (SP) * vi.y;                       \
                float wy = fmaf((CP), vi.y, (SP) * vi.x);                   \
                vb[I].x = fmaf((CT), wx, -(ST) * vj.x);                     \
                vb[I].y = fmaf((CT), wy, -(ST) * vj.y);                     \
                vb[J].x = fmaf((ST), wx,  (CT) * vj.x);                     \
                vb[J].y = fmaf((ST), wy,  (CT) * vj.y);                     \
            }                                                               \
        } while (0)

        // k=4..13: (i,j), theta, phi
        ROT(0,1, ds[3],  dc[3],  ds[0],  dc[0]);    // k=4  xs3 / xs0
        ROT(2,3, ds[4],  dc[4],  ds[1],  dc[1]);    // k=5  xs4 / xs1
        ROT(4,5, ds[5],  dc[5],  ds[2],  dc[2]);    // k=6  xs5 / xs2
        ROT(1,2, s_sin[4], s_cos[4], s_sin[8],  s_cos[8]);   // k=7  pth4 / pphi0
        ROT(3,4, s_sin[5], s_cos[5], s_sin[9],  s_cos[9]);   // k=8  pth5 / pphi1
        ROT(0,1, ds[9],  dc[9],  ds[6],  dc[6]);    // k=9  xs9 / xs6
        ROT(2,3, ds[10], dc[10], ds[7],  dc[7]);    // k=10 xs10/ xs7
        ROT(4,5, ds[11], dc[11], ds[8],  dc[8]);    // k=11 xs11/ xs8
        ROT(1,2, s_sin[6], s_cos[6], s_sin[10], s_cos[10]);  // k=12 pth6 / pphi2
        ROT(3,4, s_sin[7], s_cos[7], s_sin[11], s_cos[11]);  // k=13 pth7 / pphi3
        #undef ROT

        // ---- 15 pair amplitudes: amp = va[i]*vb[j] + va[j]*vb[i] ----
        const int OA[NPAIR] = {0,0,0,0,0,1,1,1,1,2,2,2,3,3,4};
        const int OB[NPAIR] = {1,2,3,4,5,2,3,4,5,3,4,5,4,5,5};

        float m2[NPAIR];
        float s = 0.f;
        #pragma unroll
        for (int p = 0; p < NPAIR; p++) {
            const int i = OA[p], j = OB[p];
            float ax = va[i].x * vb[j].x - va[i].y * vb[j].y
                     + va[j].x * vb[i].x - va[j].y * vb[i].y;
            float ay = va[i].x * vb[j].y + va[i].y * vb[j].x
                     + va[j].x * vb[i].y + va[j].y * vb[i].x;
            m2[p] = fmaf(ax, ax, ay * ay);
            s += m2[p];
        }

        // out[p] = sqrt(m2[p]) / max(sqrt(s), 1e-12) = sqrt(m2[p] / max(s, 1e-24))
        float t = __frcp_rn(fmaxf(s, 1e-24f));
        float* so = s_out + tid * NPAIR;
        #pragma unroll
        for (int p = 0; p < NPAIR; p++) {
            float u = fmaxf(m2[p] * t, 1e-30f);       // avoid rsqrt(0)*0 = NaN
            so[p] = __frsqrt_rn(u) * u;               // = sqrt(u)
        }
    }
    __syncthreads();

    // ---- coalesced block store: TPB*15 floats = TPB*15/4 float4 ----
    {
        const int block_base_row = blockIdx.x * TPB;
        int rows_here = B - block_base_row;
        if (rows_here > TPB) rows_here = TPB;
        const int nvec = (rows_here * NPAIR) / 4;            // full float4s
        const int ntail = rows_here * NPAIR - nvec * 4;
        float4* og = reinterpret_cast<float4*>(out + (size_t)block_base_row * NPAIR);
        const float4* sg = reinterpret_cast<const float4*>(s_out);
        for (int v = tid; v < nvec; v += TPB)
            og[v] = sg[v];
        // tail (only possible on a ragged last block)
        for (int e = nvec * 4 + tid; e < nvec * 4 + ntail; e += TPB)
            out[(size_t)block_base_row * NPAIR + e] = s_out[e];
    }
}

extern "C" void kernel_launch(void* const* d_in, const int* in_sizes, int n_in,
                              void* d_out, int out_size)
{
    const float* x    = (const float*)d_in[0];
    const float* pphi = (const float*)d_in[1];
    const float* pth  = (const float*)d_in[2];
    const float* kin  = (const float*)d_in[3];
    const float* bin  = (const float*)d_in[4];
    float* out = (float*)d_out;

    int B = in_sizes[0] / 12;
    int blocks = (B + TPB - 1) / TPB;
    bqnn_kernel<<<blocks, TPB>>>(x, pphi, pth, kin, bin, out, B);
}

// round 6
// speedup vs baseline: 2.2075x; 1.1575x over previous
#include <cuda_runtime.h>

// BQNN_hardware — row-pair SIMD version (R5 + alignment fix).
// Two batch rows per thread, packed into f32x2 lanes: every FMA-class op
// (Givens rotations, pair amplitudes, normalization) processes 2 rows per
// issued instruction via fma/mul/add.rn.f32x2 (FFMA2 — PTX-only on sm_103a).
// Rotations are hand-specialized for the exact zero/real sparsity pattern
// (inline asm is opaque to compiler zero-folding). Uniform trig (params) is
// precomputed once per block as duplicated float2 pairs in smem, including
// pre-negated copies, so uniform rotations need zero per-thread prep.
//
// R5 bug: s_out landed at a non-16B shared offset after inserting s_u, so the
// float4 writeback trapped (misaligned address). Fixed with __align__(16).

#define NPAIR 15
#define TPB 128
#define RPB (2 * TPB)   // rows per block

typedef unsigned long long u64;

__device__ __forceinline__ u64 pk2(float a, float b) {
    u64 r; asm("mov.b64 %0,{%1,%2};" : "=l"(r) : "f"(a), "f"(b)); return r;
}
__device__ __forceinline__ void up2(u64 v, float& a, float& b) {
    asm("mov.b64 {%0,%1},%2;" : "=f"(a), "=f"(b) : "l"(v));
}
__device__ __forceinline__ u64 f2mul(u64 a, u64 b) {
    u64 r; asm("mul.rn.f32x2 %0,%1,%2;" : "=l"(r) : "l"(a), "l"(b)); return r;
}
__device__ __forceinline__ u64 f2fma(u64 a, u64 b, u64 c) {
    u64 r; asm("fma.rn.f32x2 %0,%1,%2,%3;" : "=l"(r) : "l"(a), "l"(b), "l"(c)); return r;
}
__device__ __forceinline__ u64 f2add(u64 a, u64 b) {
    u64 r; asm("add.rn.f32x2 %0,%1,%2;" : "=l"(r) : "l"(a), "l"(b)); return r;
}
__device__ __forceinline__ u64 f2neg(u64 a) { return a ^ 0x8000000080000000ull; }
__device__ __forceinline__ float rcp_fast(float x) {
    float r; asm("rcp.approx.f32 %0,%1;" : "=f"(r) : "f"(x)); return r;
}
__device__ __forceinline__ float sqrt_fast(float x) {
    float r; asm("sqrt.approx.f32 %0,%1;" : "=f"(r) : "f"(x)); return r;
}

// ---- rotation micro-kernels (all operands packed over 2 rows) ----
// full: vi complex, vj complex
__device__ __forceinline__ void rot_full(u64& vix, u64& viy, u64& vjx, u64& vjy,
                                         u64 ct, u64 st, u64 nst,
                                         u64 cp, u64 sp, u64 nsp) {
    u64 wx = f2fma(cp, vix, f2mul(nsp, viy));
    u64 wy = f2fma(cp, viy, f2mul(sp, vix));
    u64 nix = f2fma(ct, wx, f2mul(nst, vjx));
    u64 niy = f2fma(ct, wy, f2mul(nst, vjy));
    vjx = f2fma(st, wx, f2mul(ct, vjx));
    vjy = f2fma(st, wy, f2mul(ct, vjy));
    vix = nix; viy = niy;
}
// vi real (viy==0), vj complex
__device__ __forceinline__ void rot_vireal(u64& vix, u64& viy, u64& vjx, u64& vjy,
                                           u64 ct, u64 st, u64 nst,
                                           u64 cp, u64 sp) {
    u64 wx = f2mul(cp, vix);
    u64 wy = f2mul(sp, vix);
    vix = f2fma(ct, wx, f2mul(nst, vjx));
    viy = f2fma(ct, wy, f2mul(nst, vjy));
    vjx = f2fma(st, wx, f2mul(ct, vjx));
    vjy = f2fma(st, wy, f2mul(ct, vjy));
}
// vi complex, vj zero
__device__ __forceinline__ void rot_vjzero(u64& vix, u64& viy, u64& vjx, u64& vjy,
                                           u64 ct, u64 st, u64 cp, u64 sp, u64 nsp) {
    u64 wx = f2fma(cp, vix, f2mul(nsp, viy));
    u64 wy = f2fma(cp, viy, f2mul(sp, vix));
    vix = f2mul(ct, wx); viy = f2mul(ct, wy);
    vjx = f2mul(st, wx); vjy = f2mul(st, wy);
}
// vi real, vj zero
__device__ __forceinline__ void rot_vireal_vjzero(u64& vix, u64& viy, u64& vjx, u64& vjy,
                                                  u64 ct, u64 st, u64 cp, u64 sp) {
    u64 wx = f2mul(cp, vix);
    u64 wy = f2mul(sp, vix);
    vix = f2mul(ct, wx); viy = f2mul(ct, wy);
    vjx = f2mul(st, wx); vjy = f2mul(st, wy);
}
// vi real, vj real (phi arbitrary) — result: vi complex, vj complex
__device__ __forceinline__ void rot_vireal_vjreal(u64& vix, u64& viy, u64& vjx, u64& vjy,
                                                  u64 ct, u64 st, u64 nst,
                                                  u64 cp, u64 sp) {
    u64 wx = f2mul(cp, vix);
    u64 wy = f2mul(sp, vix);
    vix = f2fma(ct, wx, f2mul(nst, vjx));
    viy = f2mul(ct, wy);
    u64 t = f2mul(ct, vjx);
    vjx = f2fma(st, wx, t);
    vjy = f2mul(st, wy);
}

__global__ __launch_bounds__(TPB)
void bqnn_kernel(const float* __restrict__ x,
                 const float* __restrict__ pphi,
                 const float* __restrict__ pth,
                 const float* __restrict__ kin,
                 const float* __restrict__ bin,
                 float* __restrict__ out,
                 int B)
{
    __shared__ __align__(16) float s_out[RPB * NPAIR];  // 15360 B staging (16B-aligned!)
    __shared__ __align__(16) float2 s_u[29];            // duplicated uniform packed values
    __shared__ float s_ts[12], s_tc[12];                // sincos of [pth0..7, pphi0..3]
    __shared__ float s_k[12], s_b[12];

    const int tid = threadIdx.x;
    const int base = blockIdx.x * RPB;
    const int rowA = base + tid;
    const int rowB = rowA + TPB;

    // ---- stage 1: param sincos + scale params ----
    if (tid < 12) {
        float a = (tid < 8) ? pth[tid] : pphi[tid - 8];
        float s, c;
        __sincosf(a, &s, &c);
        s_ts[tid] = s; s_tc[tid] = c;
        s_k[tid] = kin[tid]; s_b[tid] = bin[tid];
    }
    __syncthreads();

    // ---- stage 2: duplicated uniform slots ----
    // 0..4: initial state (c0, c2*s0, s2*s0, c3, s3); pth1 provably drops out.
    // 5+6u+r (u=0..3 for rotations k7,k8,k12,k13; th=pth[4+u], ph=pphi[u]):
    //   r: 0=ct 1=st 2=-st 3=cp 4=sp 5=-sp
    if (tid < 29) {
        float v;
        if      (tid == 0) v = s_tc[0];
        else if (tid == 1) v = s_tc[2] * s_ts[0];
        else if (tid == 2) v = s_ts[2] * s_ts[0];
        else if (tid == 3) v = s_tc[3];
        else if (tid == 4) v = s_ts[3];
        else {
            int u = (tid - 5) / 6, r = (tid - 5) % 6;
            int th = 4 + u, ph = 8 + u;
            if      (r == 0) v = s_tc[th];
            else if (r == 1) v = s_ts[th];
            else if (r == 2) v = -s_ts[th];
            else if (r == 3) v = s_tc[ph];
            else if (r == 4) v = s_ts[ph];
            else             v = -s_ts[ph];
        }
        s_u[tid] = make_float2(v, v);
    }
    __syncthreads();

    const u64* su = reinterpret_cast<const u64*>(s_u);

    // ---- load raw inputs for both rows ----
    float xA[12], xB[12];
    {
        float4 z = make_float4(0.f, 0.f, 0.f, 0.f);
        float4 a0 = z, a1 = z, a2 = z, b0 = z, b1 = z, b2 = z;
        if (rowA < B) {
            const float4* p = reinterpret_cast<const float4*>(x + (size_t)rowA * 12);
            a0 = p[0]; a1 = p[1]; a2 = p[2];
        }
        if (rowB < B) {
            const float4* p = reinterpret_cast<const float4*>(x + (size_t)rowB * 12);
            b0 = p[0]; b1 = p[1]; b2 = p[2];
        }
        xA[0]=a0.x; xA[1]=a0.y; xA[2]=a0.z; xA[3]=a0.w;
        xA[4]=a1.x; xA[5]=a1.y; xA[6]=a1.z; xA[7]=a1.w;
        xA[8]=a2.x; xA[9]=a2.y; xA[10]=a2.z; xA[11]=a2.w;
        xB[0]=b0.x; xB[1]=b0.y; xB[2]=b0.z; xB[3]=b0.w;
        xB[4]=b1.x; xB[5]=b1.y; xB[6]=b1.z; xB[7]=b1.w;
        xB[8]=b2.x; xB[9]=b2.y; xB[10]=b2.z; xB[11]=b2.w;
    }

    // ---- packed state: columns 0 and 3 of U, 2 rows per lane ----
    u64 aX[6], aY[6], bX[6], bY[6];
    #pragma unroll
    for (int i = 0; i < 6; i++) { aX[i]=0; aY[i]=0; bX[i]=0; bY[i]=0; }
    aX[0] = su[0]; aX[1] = su[1]; aX[2] = su[2];
    bX[3] = su[3]; bX[4] = su[4];

    // ---- phase A: sincos of xs0..xs5 ----
    u64 S[6], C[6];
    #pragma unroll
    for (int i = 0; i < 6; i++) {
        float vA = fmaf(xA[i], s_k[i], s_b[i]);
        float vB = fmaf(xB[i], s_k[i], s_b[i]);
        float sA, cA, sB, cB;
        __sincosf(vA, &sA, &cA);
        __sincosf(vB, &sB, &cB);
        S[i] = pk2(sA, sB); C[i] = pk2(cA, cB);
    }
    {
        u64 NS3 = f2neg(S[3]);
        u64 NS4 = f2neg(S[4]);
        // k4: ROT(0,1) th=xs3 ph=xs0 — va: real/real; vb untouched
        rot_vireal_vjreal(aX[0], aY[0], aX[1], aY[1], C[3], S[3], NS3, C[0], S[0]);
        // k5: ROT(2,3) th=xs4 ph=xs1 — va: real/zero; vb: zero/real
        rot_vireal_vjzero(aX[2], aY[2], aX[3], aY[3], C[4], S[4], C[1], S[1]);
        bX[2] = f2mul(NS4, bX[3]);
        bX[3] = f2mul(C[4], bX[3]);
        // k6: ROT(4,5) th=xs5 ph=xs2 — va untouched; vb: real/zero
        rot_vireal_vjzero(bX[4], bY[4], bX[5], bY[5], C[5], S[5], C[2], S[2]);
    }
    // k7: ROT(1,2) uniform u=0 — va full; vb: zero/real
    {
        u64 ct = su[5], st = su[6], nst = su[7], cp = su[8], sp = su[9], nsp = su[10];
        rot_full(aX[1], aY[1], aX[2], aY[2], ct, st, nst, cp, sp, nsp);
        bX[1] = f2mul(nst, bX[2]);
        bX[2] = f2mul(ct, bX[2]);
    }
    // k8: ROT(3,4) uniform u=1 — va: complex/zero; vb: real/complex
    {
        u64 ct = su[11], st = su[12], nst = su[13], cp = su[14], sp = su[15], nsp = su[16];
        rot_vjzero(aX[3], aY[3], aX[4], aY[4], ct, st, cp, sp, nsp);
        rot_vireal(bX[3], bY[3], bX[4], bY[4], ct, st, nst, cp, sp);
    }

    // ---- phase B: sincos of xs6..xs11 (index i ↔ xs[6+i]) ----
    #pragma unroll
    for (int i = 0; i < 6; i++) {
        float vA = fmaf(xA[6 + i], s_k[6 + i], s_b[6 + i]);
        float vB = fmaf(xB[6 + i], s_k[6 + i], s_b[6 + i]);
        float sA, cA, sB, cB;
        __sincosf(vA, &sA, &cA);
        __sincosf(vB, &sB, &cB);
        S[i] = pk2(sA, sB); C[i] = pk2(cA, cB);
    }
    {
        u64 NS9  = f2neg(S[3]);
        u64 NS10 = f2neg(S[4]);
        u64 NS11 = f2neg(S[5]);
        u64 NSP6 = f2neg(S[0]);
        u64 NSP7 = f2neg(S[1]);
        u64 NSP8 = f2neg(S[2]);
        // k9: ROT(0,1) th=xs9 ph=xs6 — va full; vb: zero/real
        rot_full(aX[0], aY[0], aX[1], aY[1], C[3], S[3], NS9, C[0], S[0], NSP6);
        bX[0] = f2mul(NS9, bX[1]);
        bX[1] = f2mul(C[3], bX[1]);
        // k10: ROT(2,3) th=xs10 ph=xs7 — va full; vb: real/complex
        rot_full(aX[2], aY[2], aX[3], aY[3], C[4], S[4], NS10, C[1], S[1], NSP7);
        rot_vireal(bX[2], bY[2], bX[3], bY[3], C[4], S[4], NS10, C[1], S[1]);
        // k11: ROT(4,5) th=xs11 ph=xs8 — va: complex/zero; vb full
        rot_vjzero(aX[4], aY[4], aX[5], aY[5], C[5], S[5], C[2], S[2], NSP8);
        rot_full(bX[4], bY[4], bX[5], bY[5], C[5], S[5], NS11, C[2], S[2], NSP8);
    }
    // k12: ROT(1,2) uniform u=2 — va full; vb: real/complex
    {
        u64 ct = su[17], st = su[18], nst = su[19], cp = su[20], sp = su[21], nsp = su[22];
        rot_full(aX[1], aY[1], aX[2], aY[2], ct, st, nst, cp, sp, nsp);
        rot_vireal(bX[1], bY[1], bX[2], bY[2], ct, st, nst, cp, sp);
    }
    // k13: ROT(3,4) uniform u=3 — both full
    {
        u64 ct = su[23], st = su[24], nst = su[25], cp = su[26], sp = su[27], nsp = su[28];
        rot_full(aX[3], aY[3], aX[4], aY[4], ct, st, nst, cp, sp, nsp);
        rot_full(bX[3], bY[3], bX[4], bY[4], ct, st, nst, cp, sp, nsp);
    }
    // final state: everything complex except bY[0] == 0 (exploited below)

    // ---- 15 pair amplitudes (packed): amp = a_i*b_j + a_j*b_i ----
    const int OA[NPAIR] = {0,0,0,0,0,1,1,1,1,2,2,2,3,3,4};
    const int OB[NPAIR] = {1,2,3,4,5,2,3,4,5,3,4,5,4,5,5};

    u64 nay[6];
    #pragma unroll
    for (int i = 0; i < 6; i++) nay[i] = f2neg(aY[i]);

    u64 m2[NPAIR];
    u64 s2 = 0;
    #pragma unroll
    for (int p = 0; p < NPAIR; p++) {
        const int i = OA[p], j = OB[p];
        // ax = aX_i*bX_j - aY_i*bY_j + aX_j*bX_i - aY_j*bY_i
        u64 ax = f2mul(aX[i], bX[j]);
        ax = f2fma(nay[i], bY[j], ax);
        ax = f2fma(aX[j], bX[i], ax);
        if (i != 0) ax = f2fma(nay[j], bY[i], ax);     // bY[0] == 0
        // ay = aX_i*bY_j + aY_i*bX_j + aX_j*bY_i + aY_j*bX_i
        u64 ay = f2mul(aX[i], bY[j]);
        ay = f2fma(aY[i], bX[j], ay);
        if (i != 0) ay = f2fma(aX[j], bY[i], ay);      // bY[0] == 0
        ay = f2fma(aY[j], bX[i], ay);
        m2[p] = f2fma(ay, ay, f2mul(ax, ax));
        s2 = f2add(s2, m2[p]);
    }

    // ---- normalize + abs, staged to smem ----
    {
        float sA, sB;
        up2(s2, sA, sB);
        float tA = rcp_fast(fmaxf(sA, 1e-24f));
        float tB = rcp_fast(fmaxf(sB, 1e-24f));
        u64 T = pk2(tA, tB);
        float* soA = s_out + tid * NPAIR;
        float* soB = s_out + (tid + TPB) * NPAIR;
        #pragma unroll
        for (int p = 0; p < NPAIR; p++) {
            u64 u = f2mul(m2[p], T);
            float uA, uB;
            up2(u, uA, uB);
            soA[p] = sqrt_fast(uA);
            soB[p] = sqrt_fast(uB);
        }
    }
    __syncthreads();

    // ---- coalesced float4 writeback ----
    {
        int rows_here = B - base;
        if (rows_here > RPB) rows_here = RPB;
        const int total = rows_here * NPAIR;
        const int nvec = total >> 2;
        float4* og = reinterpret_cast<float4*>(out + (size_t)base * NPAIR);
        const float4* sg = reinterpret_cast<const float4*>(s_out);
        for (int v = tid; v < nvec; v += TPB)
            og[v] = sg[v];
        for (int e = (nvec << 2) + tid; e < total; e += TPB)
            out[(size_t)base * NPAIR + e] = s_out[e];
    }
}

extern "C" void kernel_launch(void* const* d_in, const int* in_sizes, int n_in,
                              void* d_out, int out_size)
{
    const float* x    = (const float*)d_in[0];
    const float* pphi = (const float*)d_in[1];
    const float* pth  = (const float*)d_in[2];
    const float* kin  = (const float*)d_in[3];
    const float* bin  = (const float*)d_in[4];
    float* out = (float*)d_out;

    int B = in_sizes[0] / 12;
    int blocks = (B + RPB - 1) / RPB;
    bqnn_kernel<<<blocks, TPB>>>(x, pphi, pth, kin, bin, out, B);
}

// round 10
// speedup vs baseline: 2.2583x; 1.0230x over previous
#include <cuda_runtime.h>

// BQNN_hardware — row-pair SIMD (f32x2) version, R7: occupancy tuning.
// Two batch rows per thread packed into f32x2 lanes (FFMA2, PTX-only).
// R7 changes vs R6 (11.6us kernel, occ 29.4%, issue 36.9% — latency-bound):
//   - TPB 128 -> 64, grid 1024 -> 2048 blocks: finer block granularity so
//     SMs can hold ~13 small blocks instead of ~6 big ones; smoother fill/drain.
//   - __launch_bounds__(64, 14) nudges regs 78 -> <=73.
//   - norm accumulation tree-reduced (3 accumulators) to cut the serial tail.

#define NPAIR 15
#define TPB 64
#define RPB (2 * TPB)   // rows per block

typedef unsigned long long u64;

__device__ __forceinline__ u64 pk2(float a, float b) {
    u64 r; asm("mov.b64 %0,{%1,%2};" : "=l"(r) : "f"(a), "f"(b)); return r;
}
__device__ __forceinline__ void up2(u64 v, float& a, float& b) {
    asm("mov.b64 {%0,%1},%2;" : "=f"(a), "=f"(b) : "l"(v));
}
__device__ __forceinline__ u64 f2mul(u64 a, u64 b) {
    u64 r; asm("mul.rn.f32x2 %0,%1,%2;" : "=l"(r) : "l"(a), "l"(b)); return r;
}
__device__ __forceinline__ u64 f2fma(u64 a, u64 b, u64 c) {
    u64 r; asm("fma.rn.f32x2 %0,%1,%2,%3;" : "=l"(r) : "l"(a), "l"(b), "l"(c)); return r;
}
__device__ __forceinline__ u64 f2add(u64 a, u64 b) {
    u64 r; asm("add.rn.f32x2 %0,%1,%2;" : "=l"(r) : "l"(a), "l"(b)); return r;
}
__device__ __forceinline__ u64 f2neg(u64 a) { return a ^ 0x8000000080000000ull; }
__device__ __forceinline__ float rcp_fast(float x) {
    float r; asm("rcp.approx.f32 %0,%1;" : "=f"(r) : "f"(x)); return r;
}
__device__ __forceinline__ float sqrt_fast(float x) {
    float r; asm("sqrt.approx.f32 %0,%1;" : "=f"(r) : "f"(x)); return r;
}

// ---- rotation micro-kernels (all operands packed over 2 rows) ----
__device__ __forceinline__ void rot_full(u64& vix, u64& viy, u64& vjx, u64& vjy,
                                         u64 ct, u64 st, u64 nst,
                                         u64 cp, u64 sp, u64 nsp) {
    u64 wx = f2fma(cp, vix, f2mul(nsp, viy));
    u64 wy = f2fma(cp, viy, f2mul(sp, vix));
    u64 nix = f2fma(ct, wx, f2mul(nst, vjx));
    u64 niy = f2fma(ct, wy, f2mul(nst, vjy));
    vjx = f2fma(st, wx, f2mul(ct, vjx));
    vjy = f2fma(st, wy, f2mul(ct, vjy));
    vix = nix; viy = niy;
}
__device__ __forceinline__ void rot_vireal(u64& vix, u64& viy, u64& vjx, u64& vjy,
                                           u64 ct, u64 st, u64 nst,
                                           u64 cp, u64 sp) {
    u64 wx = f2mul(cp, vix);
    u64 wy = f2mul(sp, vix);
    vix = f2fma(ct, wx, f2mul(nst, vjx));
    viy = f2fma(ct, wy, f2mul(nst, vjy));
    vjx = f2fma(st, wx, f2mul(ct, vjx));
    vjy = f2fma(st, wy, f2mul(ct, vjy));
}
__device__ __forceinline__ void rot_vjzero(u64& vix, u64& viy, u64& vjx, u64& vjy,
                                           u64 ct, u64 st, u64 cp, u64 sp, u64 nsp) {
    u64 wx = f2fma(cp, vix, f2mul(nsp, viy));
    u64 wy = f2fma(cp, viy, f2mul(sp, vix));
    vix = f2mul(ct, wx); viy = f2mul(ct, wy);
    vjx = f2mul(st, wx); vjy = f2mul(st, wy);
}
__device__ __forceinline__ void rot_vireal_vjzero(u64& vix, u64& viy, u64& vjx, u64& vjy,
                                                  u64 ct, u64 st, u64 cp, u64 sp) {
    u64 wx = f2mul(cp, vix);
    u64 wy = f2mul(sp, vix);
    vix = f2mul(ct, wx); viy = f2mul(ct, wy);
    vjx = f2mul(st, wx); vjy = f2mul(st, wy);
}
__device__ __forceinline__ void rot_vireal_vjreal(u64& vix, u64& viy, u64& vjx, u64& vjy,
                                                  u64 ct, u64 st, u64 nst,
                                                  u64 cp, u64 sp) {
    u64 wx = f2mul(cp, vix);
    u64 wy = f2mul(sp, vix);
    vix = f2fma(ct, wx, f2mul(nst, vjx));
    viy = f2mul(ct, wy);
    u64 t = f2mul(ct, vjx);
    vjx = f2fma(st, wx, t);
    vjy = f2mul(st, wy);
}

__global__ __launch_bounds__(TPB, 14)
void bqnn_kernel(const float* __restrict__ x,
                 const float* __restrict__ pphi,
                 const float* __restrict__ pth,
                 const float* __restrict__ kin,
                 const float* __restrict__ bin,
                 float* __restrict__ out,
                 int B)
{
    __shared__ __align__(16) float s_out[RPB * NPAIR];  // 7680 B staging (16B-aligned)
    __shared__ __align__(16) float2 s_u[29];            // duplicated uniform packed values
    __shared__ float s_ts[12], s_tc[12];                // sincos of [pth0..7, pphi0..3]
    __shared__ float s_k[12], s_b[12];

    const int tid = threadIdx.x;
    const int base = blockIdx.x * RPB;
    const int rowA = base + tid;
    const int rowB = rowA + TPB;

    // ---- stage 1: param sincos + scale params ----
    if (tid < 12) {
        float a = (tid < 8) ? pth[tid] : pphi[tid - 8];
        float s, c;
        __sincosf(a, &s, &c);
        s_ts[tid] = s; s_tc[tid] = c;
        s_k[tid] = kin[tid]; s_b[tid] = bin[tid];
    }
    __syncthreads();

    // ---- stage 2: duplicated uniform slots ----
    // 0..4: initial state (c0, c2*s0, s2*s0, c3, s3); pth1 provably drops out.
    // 5+6u+r (u=0..3 for rotations k7,k8,k12,k13; th=pth[4+u], ph=pphi[u]):
    //   r: 0=ct 1=st 2=-st 3=cp 4=sp 5=-sp
    if (tid < 29) {
        float v;
        if      (tid == 0) v = s_tc[0];
        else if (tid == 1) v = s_tc[2] * s_ts[0];
        else if (tid == 2) v = s_ts[2] * s_ts[0];
        else if (tid == 3) v = s_tc[3];
        else if (tid == 4) v = s_ts[3];
        else {
            int u = (tid - 5) / 6, r = (tid - 5) % 6;
            int th = 4 + u, ph = 8 + u;
            if      (r == 0) v = s_tc[th];
            else if (r == 1) v = s_ts[th];
            else if (r == 2) v = -s_ts[th];
            else if (r == 3) v = s_tc[ph];
            else if (r == 4) v = s_ts[ph];
            else             v = -s_ts[ph];
        }
        s_u[tid] = make_float2(v, v);
    }
    __syncthreads();

    const u64* su = reinterpret_cast<const u64*>(s_u);

    // ---- load raw inputs for both rows ----
    float xA[12], xB[12];
    {
        float4 z = make_float4(0.f, 0.f, 0.f, 0.f);
        float4 a0 = z, a1 = z, a2 = z, b0 = z, b1 = z, b2 = z;
        if (rowA < B) {
            const float4* p = reinterpret_cast<const float4*>(x + (size_t)rowA * 12);
            a0 = p[0]; a1 = p[1]; a2 = p[2];
        }
        if (rowB < B) {
            const float4* p = reinterpret_cast<const float4*>(x + (size_t)rowB * 12);
            b0 = p[0]; b1 = p[1]; b2 = p[2];
        }
        xA[0]=a0.x; xA[1]=a0.y; xA[2]=a0.z; xA[3]=a0.w;
        xA[4]=a1.x; xA[5]=a1.y; xA[6]=a1.z; xA[7]=a1.w;
        xA[8]=a2.x; xA[9]=a2.y; xA[10]=a2.z; xA[11]=a2.w;
        xB[0]=b0.x; xB[1]=b0.y; xB[2]=b0.z; xB[3]=b0.w;
        xB[4]=b1.x; xB[5]=b1.y; xB[6]=b1.z; xB[7]=b1.w;
        xB[8]=b2.x; xB[9]=b2.y; xB[10]=b2.z; xB[11]=b2.w;
    }

    // ---- packed state: columns 0 and 3 of U, 2 rows per lane ----
    u64 aX[6], aY[6], bX[6], bY[6];
    #pragma unroll
    for (int i = 0; i < 6; i++) { aX[i]=0; aY[i]=0; bX[i]=0; bY[i]=0; }
    aX[0] = su[0]; aX[1] = su[1]; aX[2] = su[2];
    bX[3] = su[3]; bX[4] = su[4];

    // ---- phase A: sincos of xs0..xs5 ----
    u64 S[6], C[6];
    #pragma unroll
    for (int i = 0; i < 6; i++) {
        float vA = fmaf(xA[i], s_k[i], s_b[i]);
        float vB = fmaf(xB[i], s_k[i], s_b[i]);
        float sA, cA, sB, cB;
        __sincosf(vA, &sA, &cA);
        __sincosf(vB, &sB, &cB);
        S[i] = pk2(sA, sB); C[i] = pk2(cA, cB);
    }
    {
        u64 NS3 = f2neg(S[3]);
        u64 NS4 = f2neg(S[4]);
        // k4: ROT(0,1) th=xs3 ph=xs0 — va: real/real; vb untouched
        rot_vireal_vjreal(aX[0], aY[0], aX[1], aY[1], C[3], S[3], NS3, C[0], S[0]);
        // k5: ROT(2,3) th=xs4 ph=xs1 — va: real/zero; vb: zero/real
        rot_vireal_vjzero(aX[2], aY[2], aX[3], aY[3], C[4], S[4], C[1], S[1]);
        bX[2] = f2mul(NS4, bX[3]);
        bX[3] = f2mul(C[4], bX[3]);
        // k6: ROT(4,5) th=xs5 ph=xs2 — va untouched; vb: real/zero
        rot_vireal_vjzero(bX[4], bY[4], bX[5], bY[5], C[5], S[5], C[2], S[2]);
    }
    // k7: ROT(1,2) uniform u=0 — va full; vb: zero/real
    {
        u64 ct = su[5], st = su[6], nst = su[7], cp = su[8], sp = su[9], nsp = su[10];
        rot_full(aX[1], aY[1], aX[2], aY[2], ct, st, nst, cp, sp, nsp);
        bX[1] = f2mul(nst, bX[2]);
        bX[2] = f2mul(ct, bX[2]);
    }
    // k8: ROT(3,4) uniform u=1 — va: complex/zero; vb: real/complex
    {
        u64 ct = su[11], st = su[12], nst = su[13], cp = su[14], sp = su[15], nsp = su[16];
        rot_vjzero(aX[3], aY[3], aX[4], aY[4], ct, st, cp, sp, nsp);
        rot_vireal(bX[3], bY[3], bX[4], bY[4], ct, st, nst, cp, sp);
    }

    // ---- phase B: sincos of xs6..xs11 (index i ↔ xs[6+i]) ----
    #pragma unroll
    for (int i = 0; i < 6; i++) {
        float vA = fmaf(xA[6 + i], s_k[6 + i], s_b[6 + i]);
        float vB = fmaf(xB[6 + i], s_k[6 + i], s_b[6 + i]);
        float sA, cA, sB, cB;
        __sincosf(vA, &sA, &cA);
        __sincosf(vB, &sB, &cB);
        S[i] = pk2(sA, sB); C[i] = pk2(cA, cB);
    }
    {
        u64 NS9  = f2neg(S[3]);
        u64 NS10 = f2neg(S[4]);
        u64 NS11 = f2neg(S[5]);
        u64 NSP6 = f2neg(S[0]);
        u64 NSP7 = f2neg(S[1]);
        u64 NSP8 = f2neg(S[2]);
        // k9: ROT(0,1) th=xs9 ph=xs6 — va full; vb: zero/real
        rot_full(aX[0], aY[0], aX[1], aY[1], C[3], S[3], NS9, C[0], S[0], NSP6);
        bX[0] = f2mul(NS9, bX[1]);
        bX[1] = f2mul(C[3], bX[1]);
        // k10: ROT(2,3) th=xs10 ph=xs7 — va full; vb: real/complex
        rot_full(aX[2], aY[2], aX[3], aY[3], C[4], S[4], NS10, C[1], S[1], NSP7);
        rot_vireal(bX[2], bY[2], bX[3], bY[3], C[4], S[4], NS10, C[1], S[1]);
        // k11: ROT(4,5) th=xs11 ph=xs8 — va: complex/zero; vb full
        rot_vjzero(aX[4], aY[4], aX[5], aY[5], C[5], S[5], C[2], S[2], NSP8);
        rot_full(bX[4], bY[4], bX[5], bY[5], C[5], S[5], NS11, C[2], S[2], NSP8);
    }
    // k12: ROT(1,2) uniform u=2 — va full; vb: real/complex
    {
        u64 ct = su[17], st = su[18], nst = su[19], cp = su[20], sp = su[21], nsp = su[22];
        rot_full(aX[1], aY[1], aX[2], aY[2], ct, st, nst, cp, sp, nsp);
        rot_vireal(bX[1], bY[1], bX[2], bY[2], ct, st, nst, cp, sp);
    }
    // k13: ROT(3,4) uniform u=3 — both full
    {
        u64 ct = su[23], st = su[24], nst = su[25], cp = su[26], sp = su[27], nsp = su[28];
        rot_full(aX[3], aY[3], aX[4], aY[4], ct, st, nst, cp, sp, nsp);
        rot_full(bX[3], bY[3], bX[4], bY[4], ct, st, nst, cp, sp, nsp);
    }
    // final state: everything complex except bY[0] == 0 (exploited below)

    // ---- 15 pair amplitudes (packed): amp = a_i*b_j + a_j*b_i ----
    const int OA[NPAIR] = {0,0,0,0,0,1,1,1,1,2,2,2,3,3,4};
    const int OB[NPAIR] = {1,2,3,4,5,2,3,4,5,3,4,5,4,5,5};

    u64 nay[6];
    #pragma unroll
    for (int i = 0; i < 6; i++) nay[i] = f2neg(aY[i]);

    u64 m2[NPAIR];
    u64 acc0 = 0, acc1 = 0, acc2 = 0;        // tree-reduced norm accumulators
    #pragma unroll
    for (int p = 0; p < NPAIR; p++) {
        const int i = OA[p], j = OB[p];
        // ax = aX_i*bX_j - aY_i*bY_j + aX_j*bX_i - aY_j*bY_i
        u64 ax = f2mul(aX[i], bX[j]);
        ax = f2fma(nay[i], bY[j], ax);
        ax = f2fma(aX[j], bX[i], ax);
        if (i != 0) ax = f2fma(nay[j], bY[i], ax);     // bY[0] == 0
        // ay = aX_i*bY_j + aY_i*bX_j + aX_j*bY_i + aY_j*bX_i
        u64 ay = f2mul(aX[i], bY[j]);
        ay = f2fma(aY[i], bX[j], ay);
        if (i != 0) ay = f2fma(aX[j], bY[i], ay);      // bY[0] == 0
        ay = f2fma(aY[j], bX[i], ay);
        m2[p] = f2fma(ay, ay, f2mul(ax, ax));
        if      (p % 3 == 0) acc0 = f2add(acc0, m2[p]);
        else if (p % 3 == 1) acc1 = f2add(acc1, m2[p]);
        else                 acc2 = f2add(acc2, m2[p]);
    }
    u64 s2 = f2add(f2add(acc0, acc1), acc2);

    // ---- normalize + abs, staged to smem ----
    {
        float sA, sB;
        up2(s2, sA, sB);
        float tA = rcp_fast(fmaxf(sA, 1e-24f));
        float tB = rcp_fast(fmaxf(sB, 1e-24f));
        u64 T = pk2(tA, tB);
        float* soA = s_out + tid * NPAIR;
        float* soB = s_out + (tid + TPB) * NPAIR;
        #pragma unroll
        for (int p = 0; p < NPAIR; p++) {
            u64 u = f2mul(m2[p], T);
            float uA, uB;
            up2(u, uA, uB);
            soA[p] = sqrt_fast(uA);
            soB[p] = sqrt_fast(uB);
        }
    }
    __syncthreads();

    // ---- coalesced float4 writeback ----
    {
        int rows_here = B - base;
        if (rows_here > RPB) rows_here = RPB;
        const int total = rows_here * NPAIR;
        const int nvec = total >> 2;
        float4* og = reinterpret_cast<float4*>(out + (size_t)base * NPAIR);
        const float4* sg = reinterpret_cast<const float4*>(s_out);
        for (int v = tid; v < nvec; v += TPB)
            og[v] = sg[v];
        for (int e = (nvec << 2) + tid; e < total; e += TPB)
            out[(size_t)base * NPAIR + e] = s_out[e];
    }
}

extern "C" void kernel_launch(void* const* d_in, const int* in_sizes, int n_in,
                              void* d_out, int out_size)
{
    const float* x    = (const float*)d_in[0];
    const float* pphi = (const float*)d_in[1];
    const float* pth  = (const float*)d_in[2];
    const float* kin  = (const float*)d_in[3];
    const float* bin  = (const float*)d_in[4];
    float* out = (float*)d_out;

    int B = in_sizes[0] / 12;
    int blocks = (B + RPB - 1) / RPB;
    bqnn_kernel<<<blocks, TPB>>>(x, pphi, pth, kin, bin, out, B);
}

// round 11
// speedup vs baseline: 2.6437x; 1.1707x over previous
#include <cuda_runtime.h>

// BQNN_hardware — row-pair SIMD (f32x2), R11: warp-decoupled version.
// Two batch rows per thread packed into f32x2 lanes (FFMA2, PTX-only).
// R11 changes vs R7 (12.5us wall, occ 34%, issue 42% — latency/serialization):
//   - NO block-level coupling: uniform params (sincos of pth/pphi, k/b) are
//     computed per-thread from broadcast __ldg (L1-hot after first warp),
//     eliminating both __syncthreads and the block-head smem staging chain.
//   - Output staging is warp-private: each warp stages its 64 rows in its own
//     smem slice, __syncwarp(), and writes back coalesced float4 itself.
//   - TPB=128, launch_bounds(128,4) (<=128 regs), grid=1024.

#define NPAIR 15
#define TPB 128
#define RPW 64              // rows per warp (2 per lane)
#define RPB (TPB * 2)       // rows per block

typedef unsigned long long u64;

__device__ __forceinline__ u64 pk2(float a, float b) {
    u64 r; asm("mov.b64 %0,{%1,%2};" : "=l"(r) : "f"(a), "f"(b)); return r;
}
__device__ __forceinline__ void up2(u64 v, float& a, float& b) {
    asm("mov.b64 {%0,%1},%2;" : "=f"(a), "=f"(b) : "l"(v));
}
__device__ __forceinline__ u64 f2mul(u64 a, u64 b) {
    u64 r; asm("mul.rn.f32x2 %0,%1,%2;" : "=l"(r) : "l"(a), "l"(b)); return r;
}
__device__ __forceinline__ u64 f2fma(u64 a, u64 b, u64 c) {
    u64 r; asm("fma.rn.f32x2 %0,%1,%2,%3;" : "=l"(r) : "l"(a), "l"(b), "l"(c)); return r;
}
__device__ __forceinline__ u64 f2add(u64 a, u64 b) {
    u64 r; asm("add.rn.f32x2 %0,%1,%2;" : "=l"(r) : "l"(a), "l"(b)); return r;
}
__device__ __forceinline__ u64 f2neg(u64 a) { return a ^ 0x8000000080000000ull; }
__device__ __forceinline__ float rcp_fast(float x) {
    float r; asm("rcp.approx.f32 %0,%1;" : "=f"(r) : "f"(x)); return r;
}
__device__ __forceinline__ float sqrt_fast(float x) {
    float r; asm("sqrt.approx.f32 %0,%1;" : "=f"(r) : "f"(x)); return r;
}

// ---- rotation micro-kernels (operands packed over 2 rows) ----
__device__ __forceinline__ void rot_full(u64& vix, u64& viy, u64& vjx, u64& vjy,
                                         u64 ct, u64 st, u64 nst,
                                         u64 cp, u64 sp, u64 nsp) {
    u64 wx = f2fma(cp, vix, f2mul(nsp, viy));
    u64 wy = f2fma(cp, viy, f2mul(sp, vix));
    u64 nix = f2fma(ct, wx, f2mul(nst, vjx));
    u64 niy = f2fma(ct, wy, f2mul(nst, vjy));
    vjx = f2fma(st, wx, f2mul(ct, vjx));
    vjy = f2fma(st, wy, f2mul(ct, vjy));
    vix = nix; viy = niy;
}
__device__ __forceinline__ void rot_vireal(u64& vix, u64& viy, u64& vjx, u64& vjy,
                                           u64 ct, u64 st, u64 nst,
                                           u64 cp, u64 sp) {
    u64 wx = f2mul(cp, vix);
    u64 wy = f2mul(sp, vix);
    vix = f2fma(ct, wx, f2mul(nst, vjx));
    viy = f2fma(ct, wy, f2mul(nst, vjy));
    vjx = f2fma(st, wx, f2mul(ct, vjx));
    vjy = f2fma(st, wy, f2mul(ct, vjy));
}
__device__ __forceinline__ void rot_vjzero(u64& vix, u64& viy, u64& vjx, u64& vjy,
                                           u64 ct, u64 st, u64 cp, u64 sp, u64 nsp) {
    u64 wx = f2fma(cp, vix, f2mul(nsp, viy));
    u64 wy = f2fma(cp, viy, f2mul(sp, vix));
    vix = f2mul(ct, wx); viy = f2mul(ct, wy);
    vjx = f2mul(st, wx); vjy = f2mul(st, wy);
}
__device__ __forceinline__ void rot_vireal_vjzero(u64& vix, u64& viy, u64& vjx, u64& vjy,
                                                  u64 ct, u64 st, u64 cp, u64 sp) {
    u64 wx = f2mul(cp, vix);
    u64 wy = f2mul(sp, vix);
    vix = f2mul(ct, wx); viy = f2mul(ct, wy);
    vjx = f2mul(st, wx); vjy = f2mul(st, wy);
}
__device__ __forceinline__ void rot_vireal_vjreal(u64& vix, u64& viy, u64& vjx, u64& vjy,
                                                  u64 ct, u64 st, u64 nst,
                                                  u64 cp, u64 sp) {
    u64 wx = f2mul(cp, vix);
    u64 wy = f2mul(sp, vix);
    vix = f2fma(ct, wx, f2mul(nst, vjx));
    viy = f2mul(ct, wy);
    u64 t = f2mul(ct, vjx);
    vjx = f2fma(st, wx, t);
    vjy = f2mul(st, wy);
}

__global__ __launch_bounds__(TPB, 4)
void bqnn_kernel(const float* __restrict__ x,
                 const float* __restrict__ pphi,
                 const float* __restrict__ pth,
                 const float* __restrict__ kin,
                 const float* __restrict__ bin,
                 float* __restrict__ out,
                 int B)
{
    __shared__ __align__(16) float s_out[RPB * NPAIR];  // 15360 B, warp-sliced

    const int tid  = threadIdx.x;
    const int lane = tid & 31;
    const int wid  = tid >> 5;
    const int wbase = blockIdx.x * RPB + wid * RPW;     // first row of this warp
    const int rowA = wbase + lane;
    const int rowB = rowA + 32;

    // ---- per-thread uniform params (broadcast __ldg, L1-hot; no barriers) ----
    // sincos of pth0, pth2, pth3 (initial state; pth1 drops out),
    // pth4..7 (uct/ust), pphi0..3 (ucp/usp).
    float s0, c0, s2p, c2p, s3p, c3p;
    __sincosf(__ldg(pth + 0), &s0,  &c0);
    __sincosf(__ldg(pth + 2), &s2p, &c2p);
    __sincosf(__ldg(pth + 3), &s3p, &c3p);
    float uct[4], ust[4], ucp[4], usp[4];
    #pragma unroll
    for (int u = 0; u < 4; u++) {
        __sincosf(__ldg(pth + 4 + u), &ust[u], &uct[u]);
        __sincosf(__ldg(pphi + u),    &usp[u], &ucp[u]);
    }

    // ---- load raw inputs for both rows ----
    float xA[12], xB[12];
    {
        float4 z = make_float4(0.f, 0.f, 0.f, 0.f);
        float4 a0 = z, a1 = z, a2 = z, b0 = z, b1 = z, b2 = z;
        if (rowA < B) {
            const float4* p = reinterpret_cast<const float4*>(x + (size_t)rowA * 12);
            a0 = p[0]; a1 = p[1]; a2 = p[2];
        }
        if (rowB < B) {
            const float4* p = reinterpret_cast<const float4*>(x + (size_t)rowB * 12);
            b0 = p[0]; b1 = p[1]; b2 = p[2];
        }
        xA[0]=a0.x; xA[1]=a0.y; xA[2]=a0.z; xA[3]=a0.w;
        xA[4]=a1.x; xA[5]=a1.y; xA[6]=a1.z; xA[7]=a1.w;
        xA[8]=a2.x; xA[9]=a2.y; xA[10]=a2.z; xA[11]=a2.w;
        xB[0]=b0.x; xB[1]=b0.y; xB[2]=b0.z; xB[3]=b0.w;
        xB[4]=b1.x; xB[5]=b1.y; xB[6]=b1.z; xB[7]=b1.w;
        xB[8]=b2.x; xB[9]=b2.y; xB[10]=b2.z; xB[11]=b2.w;
    }

    // ---- packed state: columns 0 and 3 of U, 2 rows per lane ----
    // initial state (k0..k3 folded, phi=0, basis vectors):
    u64 aX[6], aY[6], bX[6], bY[6];
    #pragma unroll
    for (int i = 0; i < 6; i++) { aX[i]=0; aY[i]=0; bX[i]=0; bY[i]=0; }
    {
        float v1 = c2p * s0, v2 = s2p * s0;
        aX[0] = pk2(c0, c0); aX[1] = pk2(v1, v1); aX[2] = pk2(v2, v2);
        bX[3] = pk2(c3p, c3p); bX[4] = pk2(s3p, s3p);
    }

    // ---- phase A: sincos of xs0..xs5 ----
    u64 S[6], C[6];
    #pragma unroll
    for (int i = 0; i < 6; i++) {
        float vA = fmaf(xA[i], __ldg(kin + i), __ldg(bin + i));
        float vB = fmaf(xB[i], __ldg(kin + i), __ldg(bin + i));
        float sA, cA, sB, cB;
        __sincosf(vA, &sA, &cA);
        __sincosf(vB, &sB, &cB);
        S[i] = pk2(sA, sB); C[i] = pk2(cA, cB);
    }
    {
        u64 NS3 = f2neg(S[3]);
        u64 NS4 = f2neg(S[4]);
        // k4: ROT(0,1) th=xs3 ph=xs0 — va: real/real; vb untouched
        rot_vireal_vjreal(aX[0], aY[0], aX[1], aY[1], C[3], S[3], NS3, C[0], S[0]);
        // k5: ROT(2,3) th=xs4 ph=xs1 — va: real/zero; vb: zero/real
        rot_vireal_vjzero(aX[2], aY[2], aX[3], aY[3], C[4], S[4], C[1], S[1]);
        bX[2] = f2mul(NS4, bX[3]);
        bX[3] = f2mul(C[4], bX[3]);
        // k6: ROT(4,5) th=xs5 ph=xs2 — va untouched; vb: real/zero
        rot_vireal_vjzero(bX[4], bY[4], bX[5], bY[5], C[5], S[5], C[2], S[2]);
    }
    // k7: ROT(1,2) uniform u=0 — va full; vb: zero/real
    {
        u64 ct = pk2(uct[0], uct[0]), st = pk2(ust[0], ust[0]), nst = f2neg(st);
        u64 cp = pk2(ucp[0], ucp[0]), sp = pk2(usp[0], usp[0]), nsp = f2neg(sp);
        rot_full(aX[1], aY[1], aX[2], aY[2], ct, st, nst, cp, sp, nsp);
        bX[1] = f2mul(nst, bX[2]);
        bX[2] = f2mul(ct, bX[2]);
    }
    // k8: ROT(3,4) uniform u=1 — va: complex/zero; vb: real/complex
    {
        u64 ct = pk2(uct[1], uct[1]), st = pk2(ust[1], ust[1]), nst = f2neg(st);
        u64 cp = pk2(ucp[1], ucp[1]), sp = pk2(usp[1], usp[1]), nsp = f2neg(sp);
        rot_vjzero(aX[3], aY[3], aX[4], aY[4], ct, st, cp, sp, nsp);
        rot_vireal(bX[3], bY[3], bX[4], bY[4], ct, st, nst, cp, sp);
    }

    // ---- phase B: sincos of xs6..xs11 (index i ↔ xs[6+i]) ----
    #pragma unroll
    for (int i = 0; i < 6; i++) {
        float vA = fmaf(xA[6 + i], __ldg(kin + 6 + i), __ldg(bin + 6 + i));
        float vB = fmaf(xB[6 + i], __ldg(kin + 6 + i), __ldg(bin + 6 + i));
        float sA, cA, sB, cB;
        __sincosf(vA, &sA, &cA);
        __sincosf(vB, &sB, &cB);
        S[i] = pk2(sA, sB); C[i] = pk2(cA, cB);
    }
    {
        u64 NS9  = f2neg(S[3]);
        u64 NS10 = f2neg(S[4]);
        u64 NS11 = f2neg(S[5]);
        u64 NSP6 = f2neg(S[0]);
        u64 NSP7 = f2neg(S[1]);
        u64 NSP8 = f2neg(S[2]);
        // k9: ROT(0,1) th=xs9 ph=xs6 — va full; vb: zero/real
        rot_full(aX[0], aY[0], aX[1], aY[1], C[3], S[3], NS9, C[0], S[0], NSP6);
        bX[0] = f2mul(NS9, bX[1]);
        bX[1] = f2mul(C[3], bX[1]);
        // k10: ROT(2,3) th=xs10 ph=xs7 — va full; vb: real/complex
        rot_full(aX[2], aY[2], aX[3], aY[3], C[4], S[4], NS10, C[1], S[1], NSP7);
        rot_vireal(bX[2], bY[2], bX[3], bY[3], C[4], S[4], NS10, C[1], S[1]);
        // k11: ROT(4,5) th=xs11 ph=xs8 — va: complex/zero; vb full
        rot_vjzero(aX[4], aY[4], aX[5], aY[5], C[5], S[5], C[2], S[2], NSP8);
        rot_full(bX[4], bY[4], bX[5], bY[5], C[5], S[5], NS11, C[2], S[2], NSP8);
    }
    // k12: ROT(1,2) uniform u=2 — va full; vb: real/complex
    {
        u64 ct = pk2(uct[2], uct[2]), st = pk2(ust[2], ust[2]), nst = f2neg(st);
        u64 cp = pk2(ucp[2], ucp[2]), sp = pk2(usp[2], usp[2]), nsp = f2neg(sp);
        rot_full(aX[1], aY[1], aX[2], aY[2], ct, st, nst, cp, sp, nsp);
        rot_vireal(bX[1], bY[1], bX[2], bY[2], ct, st, nst, cp, sp);
    }
    // k13: ROT(3,4) uniform u=3 — both full
    {
        u64 ct = pk2(uct[3], uct[3]), st = pk2(ust[3], ust[3]), nst = f2neg(st);
        u64 cp = pk2(ucp[3], ucp[3]), sp = pk2(usp[3], usp[3]), nsp = f2neg(sp);
        rot_full(aX[3], aY[3], aX[4], aY[4], ct, st, nst, cp, sp, nsp);
        rot_full(bX[3], bY[3], bX[4], bY[4], ct, st, nst, cp, sp, nsp);
    }
    // final state: everything complex except bY[0] == 0 (exploited below)

    // ---- 15 pair amplitudes (packed): amp = a_i*b_j + a_j*b_i ----
    const int OA[NPAIR] = {0,0,0,0,0,1,1,1,1,2,2,2,3,3,4};
    const int OB[NPAIR] = {1,2,3,4,5,2,3,4,5,3,4,5,4,5,5};

    u64 nay[6];
    #pragma unroll
    for (int i = 0; i < 6; i++) nay[i] = f2neg(aY[i]);

    u64 m2[NPAIR];
    u64 acc0 = 0, acc1 = 0, acc2 = 0;
    #pragma unroll
    for (int p = 0; p < NPAIR; p++) {
        const int i = OA[p], j = OB[p];
        u64 ax = f2mul(aX[i], bX[j]);
        ax = f2fma(nay[i], bY[j], ax);
        ax = f2fma(aX[j], bX[i], ax);
        if (i != 0) ax = f2fma(nay[j], bY[i], ax);     // bY[0] == 0
        u64 ay = f2mul(aX[i], bY[j]);
        ay = f2fma(aY[i], bX[j], ay);
        if (i != 0) ay = f2fma(aX[j], bY[i], ay);      // bY[0] == 0
        ay = f2fma(aY[j], bX[i], ay);
        m2[p] = f2fma(ay, ay, f2mul(ax, ax));
        if      (p % 3 == 0) acc0 = f2add(acc0, m2[p]);
        else if (p % 3 == 1) acc1 = f2add(acc1, m2[p]);
        else                 acc2 = f2add(acc2, m2[p]);
    }
    u64 s2 = f2add(f2add(acc0, acc1), acc2);

    // ---- normalize + abs, staged to this warp's smem slice ----
    {
        float sA, sB;
        up2(s2, sA, sB);
        float tA = rcp_fast(fmaxf(sA, 1e-24f));
        float tB = rcp_fast(fmaxf(sB, 1e-24f));
        u64 T = pk2(tA, tB);
        float* soA = s_out + (wid * RPW + lane) * NPAIR;
        float* soB = soA + 32 * NPAIR;
        #pragma unroll
        for (int p = 0; p < NPAIR; p++) {
            u64 u = f2mul(m2[p], T);
            float uA, uB;
            up2(u, uA, uB);
            soA[p] = sqrt_fast(uA);
            soB[p] = sqrt_fast(uB);
        }
    }
    __syncwarp();

    // ---- warp-private coalesced float4 writeback (64 rows = 960 floats) ----
    {
        int rows_here = B - wbase;
        if (rows_here > 0) {
            if (rows_here > RPW) rows_here = RPW;
            const int total = rows_here * NPAIR;
            const int nvec = total >> 2;
            float4* og = reinterpret_cast<float4*>(out + (size_t)wbase * NPAIR);
            const float* ss = s_out + wid * RPW * NPAIR;
            const float4* sg = reinterpret_cast<const float4*>(ss);
            for (int v = lane; v < nvec; v += 32)
                og[v] = sg[v];
            for (int e = (nvec << 2) + lane; e < total; e += 32)
                out[(size_t)wbase * NPAIR + e] = ss[e];
        }
    }
}

extern "C" void kernel_launch(void* const* d_in, const int* in_sizes, int n_in,
                              void* d_out, int out_size)
{
    const float* x    = (const float*)d_in[0];
    const float* pphi = (const float*)d_in[1];
    const float* pth  = (const float*)d_in[2];
    const float* kin  = (const float*)d_in[3];
    const float* bin  = (const float*)d_in[4];
    float* out = (float*)d_out;

    int B = in_sizes[0] / 12;
    int blocks = (B + RPB - 1) / RPB;
    bqnn_kernel<<<blocks, TPB>>>(x, pphi, pth, kin, bin, out, B);
}